// round 9
// baseline (speedup 1.0000x reference)
#include <cuda_runtime.h>
#include <math.h>

#define Bb 64
#define Cc 8
#define Nn 2048
#define Tt 64
#define NSPLIT 16
#define NROWS (Nn / NSPLIT)                 // 128 rows per reduce block
#define BPG 8                               // batches per group: x[g] = 32 MB
#define GROUPS (Bb / BPG)                   // 8
#define RED_BLOCKS (BPG * Cc * NSPLIT)      // 1024
#define AGG_BLOCKS (BPG * 128)              // 1024
#define NT4 (Nn * Tt / 4)                   // 32768 float4 per (b,c)

// scratch
__device__ float g_part[Bb * Cc * NSPLIT * Tt];   // 2 MB
__device__ float g_att[Bb * Cc * Cc];

// ---------------------------------------------------------------------------
// Reduce for group g: plain loads (PLANT x[g] in L2 — no evict-first here!).
// 1024 blocks; block = (b,c,split of 128 rows); 16 row-threads x 16 lanes.
// ---------------------------------------------------------------------------
__global__ void __launch_bounds__(256)
k_reduce(const float* __restrict__ x, const float* __restrict__ alpha, int g) {
    int r     = blockIdx.x;
    int split = r & (NSPLIT - 1);
    int bcl   = r >> 4;                      // 0..63
    int b     = g * BPG + (bcl >> 3);
    int c     = bcl & 7;
    const float* xp = x + ((long)(b * Cc + c)) * Nn * Tt + (long)split * NROWS * Tt;

    __shared__ float s_alpha[NROWS];
    __shared__ float4 s_red[256];

    int tid = threadIdx.x;
    if (tid < NROWS) s_alpha[tid] = alpha[split * NROWS + tid];
    __syncthreads();

    int t4 = tid & 15, row = tid >> 4;
    float4 acc = make_float4(0.f, 0.f, 0.f, 0.f);
    #pragma unroll
    for (int i = 0; i < NROWS / 16; i++) {   // 8 iters
        int nl = row + i * 16;
        float4 v = reinterpret_cast<const float4*>(xp + (long)nl * Tt)[t4];
        float a = s_alpha[nl];
        acc.x += v.x * a; acc.y += v.y * a;
        acc.z += v.z * a; acc.w += v.w * a;
    }

    s_red[tid] = acc;
    __syncthreads();
    #pragma unroll
    for (int off = 8; off >= 1; off >>= 1) {
        if (row < off) {
            float4 o = s_red[(row + off) * 16 + t4];
            acc.x += o.x; acc.y += o.y; acc.z += o.z; acc.w += o.w;
            s_red[tid] = acc;
        }
        __syncthreads();
    }
    if (row == 0)
        reinterpret_cast<float4*>(
            g_part + ((long)(b * Cc + c) * NSPLIT + split) * Tt)[t4] = acc;
}

// ---------------------------------------------------------------------------
// att for group g: BPG blocks x 64 threads.
// ---------------------------------------------------------------------------
__global__ void __launch_bounds__(64)
k_att(const float* __restrict__ Wc, int g) {
    int b = g * BPG + blockIdx.x;
    int tid = threadIdx.x;

    __shared__ float sW[64 * 64];
    __shared__ float sk[8 * 64];
    __shared__ float sm[8 * 64];
    __shared__ float ssc[64];

    for (int i = tid; i < 64 * 64; i += 64) sW[i] = Wc[i];
    for (int i = tid; i < 8 * 64; i += 64) {
        int c = i >> 6, t = i & 63;
        const float* gp = g_part + ((long)(b * Cc + c) * NSPLIT) * Tt + t;
        float s = 0.f;
        #pragma unroll
        for (int p = 0; p < NSPLIT; p++) s += gp[p * Tt];
        sk[i] = s;
    }
    __syncthreads();

    #pragma unroll
    for (int c = 0; c < 8; c++) {
        float acc = 0.f;
        #pragma unroll
        for (int t = 0; t < 64; t++) acc += sk[c * 64 + t] * sW[t * 64 + tid];
        sm[c * 64 + tid] = acc;
    }
    __syncthreads();

    int c = tid >> 3, d = tid & 7;
    float sc = 0.f;
    #pragma unroll
    for (int s = 0; s < 64; s++) sc += sm[c * 64 + s] * sk[d * 64 + s];
    ssc[tid] = sc;
    __syncthreads();

    if (tid < 8) {
        float mx = -1e30f;
        #pragma unroll
        for (int j = 0; j < 8; j++) mx = fmaxf(mx, ssc[tid * 8 + j]);
        float e[8], sum = 0.f;
        #pragma unroll
        for (int j = 0; j < 8; j++) { e[j] = __expf(ssc[tid * 8 + j] - mx); sum += e[j]; }
        float inv = 1.f / sum;
        #pragma unroll
        for (int j = 0; j < 8; j++)
            g_att[b * Cc * Cc + tid * Cc + j] = e[j] * inv;
    }
}

// ---------------------------------------------------------------------------
// agg for group g: x from L2 (__ldcs, last use), streaming stores.
// Triggers PDL completion so reduce(g+1) can start alongside.
// ---------------------------------------------------------------------------
__global__ void __launch_bounds__(256)
k_agg(const float* __restrict__ x, float* __restrict__ out, int g) {
#if __CUDA_ARCH__ >= 900
    cudaTriggerProgrammaticLaunchCompletion();
#endif
    int bl    = blockIdx.x >> 7;             // 0..7
    int chunk = blockIdx.x & 127;
    int b     = g * BPG + bl;
    int tid   = threadIdx.x;

    __shared__ float satt[64];
    if (tid < 64) satt[tid] = g_att[b * 64 + tid];
    __syncthreads();

    int p = chunk * 256 + tid;
    const float4* xb = reinterpret_cast<const float4*>(x + (long)b * Cc * Nn * Tt);
    float4*       ob = reinterpret_cast<float4*>(out + (long)b * Cc * Nn * Tt);

    float4 v[8];
    #pragma unroll
    for (int i = 0; i < 8; i++)
        v[i] = __ldcs(&xb[(long)i * NT4 + p]);   // L2 hit, evict-first (last use)

    #pragma unroll
    for (int c = 0; c < 8; c++) {
        float4 acc = make_float4(0.f, 0.f, 0.f, 0.f);
        #pragma unroll
        for (int i = 0; i < 8; i++) {
            float a = satt[c * 8 + i];
            acc.x += a * v[i].x; acc.y += a * v[i].y;
            acc.z += a * v[i].z; acc.w += a * v[i].w;
        }
        __stcs(&ob[(long)c * NT4 + p], acc);     // evict-first: protect x in L2
    }
}

// ---------------------------------------------------------------------------
extern "C" void kernel_launch(void* const* d_in, const int* in_sizes, int n_in,
                              void* d_out, int out_size) {
    const float* x     = (const float*)d_in[0];
    const float* Wc    = (const float*)d_in[1];
    const float* alpha = (const float*)d_in[2];
    float* out = (float*)d_out;

    // prologue
    k_reduce<<<RED_BLOCKS, 256>>>(x, alpha, 0);
    k_att<<<BPG, 64>>>(Wc, 0);

    cudaLaunchAttribute attr[1];
    attr[0].id = cudaLaunchAttributeProgrammaticStreamSerialization;
    attr[0].val.programmaticStreamSerializationAllowed = 1;

    for (int g = 0; g < GROUPS; g++) {
        k_agg<<<AGG_BLOCKS, 256>>>(x, out, g);           // primary

        if (g + 1 < GROUPS) {
            // reduce(g+1): PDL secondary — overlaps agg(g) (independent data)
            cudaLaunchConfig_t cfg = {};
            cfg.gridDim = dim3(RED_BLOCKS);
            cfg.blockDim = dim3(256);
            cfg.dynamicSmemBytes = 0;
            cfg.stream = 0;
            cfg.attrs = attr;
            cfg.numAttrs = 1;
            cudaLaunchKernelEx(&cfg, k_reduce, x, alpha, g + 1);
            k_att<<<BPG, 64>>>(Wc, g + 1);               // waits reduce(g+1) & agg(g)
        }
    }
}

// round 10
// speedup vs baseline: 1.3486x; 1.3486x over previous
#include <cuda_runtime.h>
#include <math.h>

#define Bb 64
#define Cc 8
#define Nn 2048
#define Tt 64
#define NSPLIT 4
#define NROWS (Nn / NSPLIT)                 // 512 rows per reduce block
#define RED_BLOCKS (Bb * Cc * NSPLIT)       // 2048
#define AGG_BLOCKS (Bb * 128)               // 8192
#define NT4 (Nn * Tt / 4)                   // 32768 float4 per (b,c)

// scratch
__device__ float g_part[Bb * Cc * NSPLIT * Tt];   // reduction partials (512 KB)
__device__ float g_att[Bb * Cc * Cc];             // attention weights

// ---------------------------------------------------------------------------
// Kernel 1: partial k. Block = (b, c, split); 256 threads = 16 rows x 16 lanes.
// 32 iterations, unroll 16 -> deep LDG pipeline.
// ---------------------------------------------------------------------------
__global__ void __launch_bounds__(256)
k_reduce(const float* __restrict__ x, const float* __restrict__ alpha) {
    int r     = blockIdx.x;
    int split = r & (NSPLIT - 1);
    int bc    = r >> 2;                      // b*Cc + c
    const float* xp = x + (long)bc * Nn * Tt + (long)split * NROWS * Tt;

    __shared__ float s_alpha[NROWS];         // 2 KB
    __shared__ float4 s_red[256];            // 4 KB

    int tid = threadIdx.x;
    for (int i = tid; i < NROWS; i += 256) s_alpha[i] = alpha[split * NROWS + i];
    __syncthreads();

    int t4 = tid & 15, row = tid >> 4;
    float4 acc = make_float4(0.f, 0.f, 0.f, 0.f);
    const float4* xv = reinterpret_cast<const float4*>(xp) + t4;

    #pragma unroll 16
    for (int i = 0; i < NROWS / 16; i++) {   // 32 iters
        int nl = row + i * 16;
        float4 v = __ldcs(&xv[(long)nl * 16]);
        float a = s_alpha[nl];
        acc.x += v.x * a; acc.y += v.y * a;
        acc.z += v.z * a; acc.w += v.w * a;
    }

    s_red[tid] = acc;
    __syncthreads();
    #pragma unroll
    for (int off = 8; off >= 1; off >>= 1) {
        if (row < off) {
            float4 o = s_red[(row + off) * 16 + t4];
            acc.x += o.x; acc.y += o.y; acc.z += o.z; acc.w += o.w;
            s_red[tid] = acc;
        }
        __syncthreads();
    }
    if (row == 0)
        reinterpret_cast<float4*>(
            g_part + ((long)bc * NSPLIT + split) * Tt)[t4] = acc;
}

// ---------------------------------------------------------------------------
// Kernel 2: att[b] per block. 64 blocks x 64 threads.
// ---------------------------------------------------------------------------
__global__ void __launch_bounds__(64)
k_att(const float* __restrict__ Wc) {
    int b = blockIdx.x;
    int tid = threadIdx.x;                   // 0..63

    __shared__ float sW[64 * 64];
    __shared__ float sk[8 * 64];
    __shared__ float sm[8 * 64];
    __shared__ float ssc[64];

    for (int i = tid; i < 64 * 64; i += 64) sW[i] = Wc[i];
    for (int i = tid; i < 8 * 64; i += 64) {
        int c = i >> 6, t = i & 63;
        const float* gp = g_part + ((long)(b * Cc + c) * NSPLIT) * Tt + t;
        float s = 0.f;
        #pragma unroll
        for (int p = 0; p < NSPLIT; p++) s += gp[p * Tt];
        sk[i] = s;
    }
    __syncthreads();

    #pragma unroll
    for (int c = 0; c < 8; c++) {
        float acc = 0.f;
        #pragma unroll
        for (int t = 0; t < 64; t++) acc += sk[c * 64 + t] * sW[t * 64 + tid];
        sm[c * 64 + tid] = acc;
    }
    __syncthreads();

    int c = tid >> 3, d = tid & 7;
    float sc = 0.f;
    #pragma unroll
    for (int s = 0; s < 64; s++) sc += sm[c * 64 + s] * sk[d * 64 + s];
    ssc[tid] = sc;
    __syncthreads();

    if (tid < 8) {
        float mx = -1e30f;
        #pragma unroll
        for (int j = 0; j < 8; j++) mx = fmaxf(mx, ssc[tid * 8 + j]);
        float e[8], sum = 0.f;
        #pragma unroll
        for (int j = 0; j < 8; j++) { e[j] = __expf(ssc[tid * 8 + j] - mx); sum += e[j]; }
        float inv = 1.f / sum;
        #pragma unroll
        for (int j = 0; j < 8; j++)
            g_att[b * Cc * Cc + tid * Cc + j] = e[j] * inv;
    }
}

// ---------------------------------------------------------------------------
// Kernel 3: out[b,c,n,t] = sum_i att[b,c,i] * x[b,i,n,t]
// 8192 blocks x 256 threads; MLP-8 prefetch; first store issues early.
// ---------------------------------------------------------------------------
__global__ void __launch_bounds__(256)
k_agg(const float* __restrict__ x, float* __restrict__ out) {
    int b     = blockIdx.x >> 7;             // 128 blocks per batch
    int chunk = blockIdx.x & 127;
    int tid   = threadIdx.x;

    __shared__ float satt[64];
    if (tid < 64) satt[tid] = g_att[b * 64 + tid];
    __syncthreads();

    int p = chunk * 256 + tid;
    const float4* xb = reinterpret_cast<const float4*>(x + (long)b * Cc * Nn * Tt) + p;
    float4*       ob = reinterpret_cast<float4*>(out + (long)b * Cc * Nn * Tt) + p;

    // prefetch all 8 channel vectors (MLP = 8); x dead after this -> evict-first
    float4 v[8];
    #pragma unroll
    for (int i = 0; i < 8; i++)
        v[i] = __ldcs(xb + (long)i * NT4);

    #pragma unroll
    for (int c = 0; c < 8; c++) {
        float a0 = satt[c * 8];
        float4 acc;
        acc.x = a0 * v[0].x; acc.y = a0 * v[0].y;
        acc.z = a0 * v[0].z; acc.w = a0 * v[0].w;
        #pragma unroll
        for (int i = 1; i < 8; i++) {
            float a = satt[c * 8 + i];
            acc.x += a * v[i].x; acc.y += a * v[i].y;
            acc.z += a * v[i].z; acc.w += a * v[i].w;
        }
        __stcs(ob + (long)c * NT4, acc);
    }
}

// ---------------------------------------------------------------------------
extern "C" void kernel_launch(void* const* d_in, const int* in_sizes, int n_in,
                              void* d_out, int out_size) {
    const float* x     = (const float*)d_in[0];
    const float* Wc    = (const float*)d_in[1];
    const float* alpha = (const float*)d_in[2];
    float* out = (float*)d_out;

    k_reduce<<<RED_BLOCKS, 256>>>(x, alpha);
    k_att<<<Bb, 64>>>(Wc);
    k_agg<<<AGG_BLOCKS, 256>>>(x, out);
}

// round 11
// speedup vs baseline: 1.4042x; 1.0412x over previous
#include <cuda_runtime.h>
#include <math.h>

#define Bb 64
#define Cc 8
#define Nn 2048
#define Tt 64
#define NSPLIT 4
#define NROWS (Nn / NSPLIT)                 // 512 rows per reduce block
#define RED_BLOCKS (Bb * Cc * NSPLIT)       // 2048 (32 per batch)
#define AGG_BLOCKS (Bb * 128)               // 8192
#define NT4 (Nn * Tt / 4)                   // 32768 float4 per (b,c)

// scratch
__device__ float g_part[Bb * Cc * NSPLIT * Tt];   // 512 KB
__device__ float g_att[Bb * Cc * Cc];
__device__ int   g_cnt[Bb];                       // zero-init; reset each run

union SmemU {
    struct { float alpha[NROWS]; float4 red[256]; } r;            // 6 KB
    struct { float W[64 * 64]; float k[8 * 64]; float m[8 * 64];
             float sc[64]; } t;                                   // ~20.5 KB
};

// ---------------------------------------------------------------------------
// Kernel 1: partial k + last-block-per-batch computes att[b].
// Block = (b, c, split); 256 threads. PLAIN loads: leave x tail in L2.
// ---------------------------------------------------------------------------
__global__ void __launch_bounds__(256)
k_reduce_att(const float* __restrict__ x, const float* __restrict__ alpha,
             const float* __restrict__ Wc) {
    __shared__ SmemU S;
    __shared__ int s_last;

    int r     = blockIdx.x;
    int split = r & (NSPLIT - 1);
    int bc    = r >> 2;                      // b*Cc + c
    int b     = bc >> 3;
    const float* xp = x + (long)bc * Nn * Tt + (long)split * NROWS * Tt;

    int tid = threadIdx.x;
    for (int i = tid; i < NROWS; i += 256) S.r.alpha[i] = alpha[split * NROWS + i];
    __syncthreads();

    int t4 = tid & 15, row = tid >> 4;
    float4 acc = make_float4(0.f, 0.f, 0.f, 0.f);
    const float4* xv = reinterpret_cast<const float4*>(xp) + t4;

    #pragma unroll 8
    for (int i = 0; i < NROWS / 16; i++) {   // 32 iters; PLAIN ld -> stays in L2
        int nl = row + i * 16;
        float4 v = xv[(long)nl * 16];
        float a = S.r.alpha[nl];
        acc.x += v.x * a; acc.y += v.y * a;
        acc.z += v.z * a; acc.w += v.w * a;
    }

    S.r.red[tid] = acc;
    __syncthreads();
    #pragma unroll
    for (int off = 8; off >= 1; off >>= 1) {
        if (row < off) {
            float4 o = S.r.red[(row + off) * 16 + t4];
            acc.x += o.x; acc.y += o.y; acc.z += o.z; acc.w += o.w;
            S.r.red[tid] = acc;
        }
        __syncthreads();
    }
    if (row == 0)
        reinterpret_cast<float4*>(
            g_part + ((long)bc * NSPLIT + split) * Tt)[t4] = acc;

    // ---- last-block-per-batch tail: compute att[b] ----
    __threadfence();
    if (tid == 0)
        s_last = (atomicAdd(&g_cnt[b], 1) == 32 - 1);
    __syncthreads();
    if (!s_last) return;

    // att for batch b (256 threads)
    for (int i = tid; i < 64 * 64; i += 256) S.t.W[i] = Wc[i];
    for (int i = tid; i < 8 * 64; i += 256) {
        int c = i >> 6, t = i & 63;
        const float* gp = g_part + ((long)(b * Cc + c) * NSPLIT) * Tt + t;
        float s = 0.f;
        #pragma unroll
        for (int p = 0; p < NSPLIT; p++) s += gp[p * Tt];
        S.t.k[i] = s;
    }
    __syncthreads();

    for (int e = tid; e < 512; e += 256) {
        int c = e >> 6, s = e & 63;
        float a2 = 0.f;
        #pragma unroll
        for (int t = 0; t < 64; t++) a2 += S.t.k[c * 64 + t] * S.t.W[t * 64 + s];
        S.t.m[e] = a2;
    }
    __syncthreads();

    if (tid < 64) {
        int c = tid >> 3, d = tid & 7;
        float sc = 0.f;
        #pragma unroll
        for (int s = 0; s < 64; s++) sc += S.t.m[c * 64 + s] * S.t.k[d * 64 + s];
        S.t.sc[tid] = sc;
    }
    __syncthreads();

    if (tid < 8) {
        float mx = -1e30f;
        #pragma unroll
        for (int j = 0; j < 8; j++) mx = fmaxf(mx, S.t.sc[tid * 8 + j]);
        float e[8], sum = 0.f;
        #pragma unroll
        for (int j = 0; j < 8; j++) { e[j] = __expf(S.t.sc[tid * 8 + j] - mx); sum += e[j]; }
        float inv = 1.f / sum;
        #pragma unroll
        for (int j = 0; j < 8; j++)
            g_att[b * Cc * Cc + tid * Cc + j] = e[j] * inv;
    }
    if (tid == 0) g_cnt[b] = 0;              // reset for next graph replay
}

// ---------------------------------------------------------------------------
// Kernel 2: aggregation, batches in REVERSE order so first reads hit the
// x-tail still resident in L2 from k_reduce_att.
// ---------------------------------------------------------------------------
__global__ void __launch_bounds__(256)
k_agg(const float* __restrict__ x, float* __restrict__ out) {
    int b     = (Bb - 1) - (blockIdx.x >> 7);    // reversed batch order
    int chunk = blockIdx.x & 127;
    int tid   = threadIdx.x;

    __shared__ float satt[64];
    if (tid < 64) satt[tid] = g_att[b * 64 + tid];
    __syncthreads();

    int p = chunk * 256 + tid;
    const float4* xb = reinterpret_cast<const float4*>(x + (long)b * Cc * Nn * Tt) + p;
    float4*       ob = reinterpret_cast<float4*>(out + (long)b * Cc * Nn * Tt) + p;

    float4 v[8];
    #pragma unroll
    for (int i = 0; i < 8; i++)
        v[i] = __ldcs(xb + (long)i * NT4);       // evict-first: x dead after this

    #pragma unroll
    for (int c = 0; c < 8; c++) {
        float a0 = satt[c * 8];
        float4 acc;
        acc.x = a0 * v[0].x; acc.y = a0 * v[0].y;
        acc.z = a0 * v[0].z; acc.w = a0 * v[0].w;
        #pragma unroll
        for (int i = 1; i < 8; i++) {
            float a = satt[c * 8 + i];
            acc.x += a * v[i].x; acc.y += a * v[i].y;
            acc.z += a * v[i].z; acc.w += a * v[i].w;
        }
        __stcs(ob + (long)c * NT4, acc);         // evict-first: protect x in L2
    }
}

// ---------------------------------------------------------------------------
extern "C" void kernel_launch(void* const* d_in, const int* in_sizes, int n_in,
                              void* d_out, int out_size) {
    const float* x     = (const float*)d_in[0];
    const float* Wc    = (const float*)d_in[1];
    const float* alpha = (const float*)d_in[2];
    float* out = (float*)d_out;

    k_reduce_att<<<RED_BLOCKS, 256>>>(x, alpha, Wc);
    k_agg<<<AGG_BLOCKS, 256>>>(x, out);
}